// round 2
// baseline (speedup 1.0000x reference)
#include <cuda_runtime.h>
#include <cstdint>

// ---------------------------------------------------------------------------
// TripletHardLoss: loss = mean(relu(max_{same}(dist) - min_{diff}(dist) + 0.3))
// dist[i][j] = sqrt(max(||xi||^2 + ||xj||^2 - 2 xi.xj, 0))
// Fused: Gram-tile GEMM + masked row max/min in epilogue. No D materialized.
// Label dtype (int32 vs int64) detected on-device.
// ---------------------------------------------------------------------------

#define MAX_N 8192
__device__ float        g_sq[MAX_N];
__device__ unsigned int g_ap[MAX_N];   // hardest positive, float bits (>=0)
__device__ unsigned int g_an[MAX_N];   // hardest negative, float bits (>=0)
__device__ int          g_lbl[MAX_N];
__device__ int          g_is64;

#define BM 128
#define BN 128
#define BK 16
#define TM 8
#define TN 8

// ---- kernel -1: detect whether Y is int64 (all high words zero) or int32 ----
__global__ void k_detect(const int* __restrict__ Yi) {
    if (threadIdx.x == 0) {
        int nz = 0;
#pragma unroll
        for (int i = 0; i < 64; i++) nz |= Yi[2 * i + 1];
        g_is64 = (nz == 0) ? 1 : 0;
    }
}

// ---- kernel 0: row sum-of-squares + scratch init + label narrow ----
__global__ void k_rowsq(const float* __restrict__ X,
                        const void* __restrict__ Y,
                        int n, int d) {
    int row = blockIdx.x;
    const float4* xr = reinterpret_cast<const float4*>(X + (size_t)row * d);
    int nv = d >> 2;
    float s = 0.f;
    for (int i = threadIdx.x; i < nv; i += blockDim.x) {
        float4 v = xr[i];
        s += v.x * v.x + v.y * v.y + v.z * v.z + v.w * v.w;
    }
    __shared__ float sh[32];
    for (int o = 16; o > 0; o >>= 1) s += __shfl_xor_sync(0xffffffffu, s, o);
    if ((threadIdx.x & 31) == 0) sh[threadIdx.x >> 5] = s;
    __syncthreads();
    if (threadIdx.x < 32) {
        float v = (threadIdx.x < (blockDim.x >> 5)) ? sh[threadIdx.x] : 0.f;
        for (int o = 16; o > 0; o >>= 1) v += __shfl_xor_sync(0xffffffffu, v, o);
        if (threadIdx.x == 0) {
            g_sq[row]  = v;
            g_ap[row]  = 0u;            // 0.0f
            g_an[row]  = 0x7F800000u;   // +inf
            g_lbl[row] = g_is64
                ? (int)reinterpret_cast<const long long*>(Y)[row]
                : reinterpret_cast<const int*>(Y)[row];
        }
    }
}

// ---- kernel 1: fused Gram GEMM + masked row max/min reduction ----
__global__ __launch_bounds__(256)
void k_gemm_reduce(const float* __restrict__ X, int n, int d) {
    __shared__ float As[BK][BM];
    __shared__ float Bs[BK][BN];
    __shared__ float Sqm[BM];
    __shared__ float Sqn[BN];
    __shared__ int   Lm[BM];
    __shared__ int   Ln[BN];

    const int t  = threadIdx.x;
    const int ty = t >> 4;      // 0..15
    const int tx = t & 15;      // 0..15
    const int m0 = blockIdx.y * BM;
    const int n0 = blockIdx.x * BN;

    // stage per-tile row metadata (256 threads cover 128+128)
    if (t < BM) {
        Sqm[t] = g_sq[m0 + t];
        Lm[t]  = g_lbl[m0 + t];
    } else {
        int c = t - BM;
        Sqn[c] = g_sq[n0 + c];
        Ln[c]  = g_lbl[n0 + c];
    }

    float acc[TM][TN];
#pragma unroll
    for (int i = 0; i < TM; i++)
#pragma unroll
        for (int j = 0; j < TN; j++) acc[i][j] = 0.f;

    // load mapping: 512 float4 per operand tile (128 rows x 4 kgroups), 2 per thread
    const int r0  = t >> 2;          // 0..63
    const int kg  = t & 3;           // 0..3
    const int kc  = kg << 2;         // k offset within tile (0,4,8,12)

    for (int k0 = 0; k0 < d; k0 += BK) {
        __syncthreads();
#pragma unroll
        for (int h = 0; h < 2; h++) {
            int row = r0 + h * 64;
            float4 va = *reinterpret_cast<const float4*>(
                X + (size_t)(m0 + row) * d + k0 + kc);
            As[kc + 0][row] = va.x;
            As[kc + 1][row] = va.y;
            As[kc + 2][row] = va.z;
            As[kc + 3][row] = va.w;
            float4 vb = *reinterpret_cast<const float4*>(
                X + (size_t)(n0 + row) * d + k0 + kc);
            Bs[kc + 0][row] = vb.x;
            Bs[kc + 1][row] = vb.y;
            Bs[kc + 2][row] = vb.z;
            Bs[kc + 3][row] = vb.w;
        }
        __syncthreads();

#pragma unroll
        for (int kk = 0; kk < BK; kk++) {
            float a[TM], b[TN];
            *reinterpret_cast<float4*>(&a[0]) =
                *reinterpret_cast<const float4*>(&As[kk][ty * TM]);
            *reinterpret_cast<float4*>(&a[4]) =
                *reinterpret_cast<const float4*>(&As[kk][ty * TM + 4]);
            *reinterpret_cast<float4*>(&b[0]) =
                *reinterpret_cast<const float4*>(&Bs[kk][tx * TN]);
            *reinterpret_cast<float4*>(&b[4]) =
                *reinterpret_cast<const float4*>(&Bs[kk][tx * TN + 4]);
#pragma unroll
            for (int i = 0; i < TM; i++)
#pragma unroll
                for (int j = 0; j < TN; j++)
                    acc[i][j] = fmaf(a[i], b[j], acc[i][j]);
        }
    }

    // epilogue: dist + mask + row-wise max/min, reduce across the 16 tx lanes
#pragma unroll
    for (int i = 0; i < TM; i++) {
        int   r  = ty * TM + i;
        float sm = Sqm[r];
        int   lm = Lm[r];
        float mp = 0.f;                          // max positive dist (diag -> 0)
        float mn = __int_as_float(0x7F800000);   // +inf
#pragma unroll
        for (int j = 0; j < TN; j++) {
            int   c    = tx * TN + j;
            float d2   = sm + Sqn[c] - 2.f * acc[i][j];
            float dist = sqrtf(fmaxf(d2, 0.f));
            if (lm == Ln[c]) mp = fmaxf(mp, dist);
            else             mn = fminf(mn, dist);
        }
#pragma unroll
        for (int o = 8; o > 0; o >>= 1) {
            mp = fmaxf(mp, __shfl_xor_sync(0xffffffffu, mp, o));
            mn = fminf(mn, __shfl_xor_sync(0xffffffffu, mn, o));
        }
        if (tx == 0) {
            atomicMax(&g_ap[m0 + r], __float_as_uint(mp));
            atomicMin(&g_an[m0 + r], __float_as_uint(mn));
        }
    }
}

// ---- kernel 2: mean hinge ----
__global__ void k_final(float* __restrict__ out, int n) {
    float s = 0.f;
    for (int i = threadIdx.x; i < n; i += blockDim.x) {
        float ap = __uint_as_float(g_ap[i]);
        float an = __uint_as_float(g_an[i]);
        s += fmaxf(ap - an + 0.3f, 0.f);
    }
    __shared__ float sh[32];
    for (int o = 16; o > 0; o >>= 1) s += __shfl_xor_sync(0xffffffffu, s, o);
    if ((threadIdx.x & 31) == 0) sh[threadIdx.x >> 5] = s;
    __syncthreads();
    if (threadIdx.x < 32) {
        float v = (threadIdx.x < (blockDim.x >> 5)) ? sh[threadIdx.x] : 0.f;
        for (int o = 16; o > 0; o >>= 1) v += __shfl_xor_sync(0xffffffffu, v, o);
        if (threadIdx.x == 0) out[0] = v / (float)n;
    }
}

extern "C" void kernel_launch(void* const* d_in, const int* in_sizes, int n_in,
                              void* d_out, int out_size) {
    const float* X = (const float*)d_in[0];
    const void*  Y = d_in[1];
    int n = in_sizes[1];                 // 4096
    int d = in_sizes[0] / n;             // 2048
    float* out = (float*)d_out;

    k_detect<<<1, 32>>>((const int*)Y);
    k_rowsq<<<n, 256>>>(X, Y, n, d);

    dim3 grid(n / BN, n / BM);
    k_gemm_reduce<<<grid, 256>>>(X, n, d);

    k_final<<<1, 256>>>(out, n);
}

// round 4
// speedup vs baseline: 1.2944x; 1.2944x over previous
#include <cuda_runtime.h>
#include <mma.h>
#include <cstdint>

using namespace nvcuda;

// ---------------------------------------------------------------------------
// TripletHardLoss: loss = mean(relu(max_{same}(dist) - min_{diff}(dist) + 0.3))
// dist[i][j] = sqrt(max(||xi||^2 + ||xj||^2 - 2 xi.xj, 0))
// Gram matrix via tf32 WMMA (mma.sync path; tcgen05 PTX is rejected by the
// harness's compute_103 virtual arch). Fused masked row max/min epilogue.
// ---------------------------------------------------------------------------

#define MAX_N 4096

__device__ float        g_sq[MAX_N];
__device__ unsigned int g_ap[MAX_N];   // hardest positive, float bits (>=0)
__device__ unsigned int g_an[MAX_N];   // hardest negative, float bits (>=0)
__device__ int          g_lbl[MAX_N];
__device__ int          g_is64;

// ---- tiling ----
#define BM 128
#define BN 128
#define KT 32                   // K per smem stage
#define LD 40                   // padded row stride (floats), %8==0 for wmma
// smem (floats): [0, 16384) = C tile (aliases A/B stage buffers), then meta
#define SMEM_FLOATS (16384 + 128 + 128)
#define SMEM_BYTES  (SMEM_FLOATS * 4)

// ---- kernel -1: detect whether Y is int64 (all high words zero) or int32 ----
__global__ void k_detect(const int* __restrict__ Yi) {
    if (threadIdx.x == 0) {
        int nz = 0;
#pragma unroll
        for (int i = 0; i < 64; i++) nz |= Yi[2 * i + 1];
        g_is64 = (nz == 0) ? 1 : 0;
    }
}

// ---- kernel 0: row sum-of-squares + scratch init + label narrow ----
__global__ void k_rowsq(const float* __restrict__ X,
                        const void* __restrict__ Y,
                        int n, int d) {
    int row = blockIdx.x;
    const float4* xr = reinterpret_cast<const float4*>(X + (size_t)row * d);
    int nv = d >> 2;
    float s = 0.f;
    for (int i = threadIdx.x; i < nv; i += blockDim.x) {
        float4 v = xr[i];
        s += v.x * v.x + v.y * v.y + v.z * v.z + v.w * v.w;
    }
    __shared__ float sh[32];
    for (int o = 16; o > 0; o >>= 1) s += __shfl_xor_sync(0xffffffffu, s, o);
    if ((threadIdx.x & 31) == 0) sh[threadIdx.x >> 5] = s;
    __syncthreads();
    if (threadIdx.x < 32) {
        float v = (threadIdx.x < (blockDim.x >> 5)) ? sh[threadIdx.x] : 0.f;
        for (int o = 16; o > 0; o >>= 1) v += __shfl_xor_sync(0xffffffffu, v, o);
        if (threadIdx.x == 0) {
            g_sq[row]  = v;
            g_ap[row]  = 0u;
            g_an[row]  = 0x7F800000u;   // +inf
            g_lbl[row] = g_is64
                ? (int)reinterpret_cast<const long long*>(Y)[row]
                : reinterpret_cast<const int*>(Y)[row];
        }
    }
}

// ---- kernel 1: fused tf32-WMMA Gram GEMM + masked row max/min ----
__global__ __launch_bounds__(256)
void k_wmma(const float* __restrict__ X, int n, int d) {
    extern __shared__ __align__(16) float smf[];
    float* As  = smf;              // 128 x LD   (5120 floats)
    float* Bs  = smf + BM * LD;    // 128 x LD   (5120 floats)
    float* Cs  = smf;              // 128 x 128  (aliases A/B, epilogue only)
    float* sqn = smf + 16384;      // 128 floats
    int*   lbn = reinterpret_cast<int*>(smf + 16384 + 128);

    const int t   = threadIdx.x;
    const int wid = t >> 5;
    const int m0  = blockIdx.y * BM;
    const int n0  = blockIdx.x * BN;
    const int wm  = wid & 3;       // warp row 0..3  (32 rows each)
    const int wn  = wid >> 2;      // warp col 0..1  (64 cols each)

    if (t < BN) {
        sqn[t] = g_sq[n0 + t];
        lbn[t] = g_lbl[n0 + t];
    }

    wmma::fragment<wmma::accumulator, 16, 16, 8, float> cf[2][4];
#pragma unroll
    for (int i = 0; i < 2; i++)
#pragma unroll
        for (int j = 0; j < 4; j++) wmma::fill_fragment(cf[i][j], 0.0f);

    for (int k0 = 0; k0 < d; k0 += KT) {
        __syncthreads();
        // stage A (rows m0..m0+127) and B (rows n0..n0+127), KT floats each
#pragma unroll
        for (int q = 0; q < 4; q++) {
            int chunk = t + q * 256;          // 0..1023
            int row   = chunk >> 3;           // 0..127
            int c4    = (chunk & 7) << 2;     // 0,4,...,28
            float4 va = *reinterpret_cast<const float4*>(
                X + (size_t)(m0 + row) * d + k0 + c4);
            *reinterpret_cast<float4*>(As + row * LD + c4) = va;
            float4 vb = *reinterpret_cast<const float4*>(
                X + (size_t)(n0 + row) * d + k0 + c4);
            *reinterpret_cast<float4*>(Bs + row * LD + c4) = vb;
        }
        __syncthreads();

#pragma unroll
        for (int kk = 0; kk < KT; kk += 8) {
            wmma::fragment<wmma::matrix_a, 16, 16, 8,
                           wmma::precision::tf32, wmma::row_major> af[2];
            wmma::fragment<wmma::matrix_b, 16, 16, 8,
                           wmma::precision::tf32, wmma::col_major> bf[4];
#pragma unroll
            for (int i = 0; i < 2; i++) {
                wmma::load_matrix_sync(af[i],
                    As + (wm * 32 + i * 16) * LD + kk, LD);
#pragma unroll
                for (int e = 0; e < af[i].num_elements; e++)
                    af[i].x[e] = wmma::__float_to_tf32(af[i].x[e]);
            }
#pragma unroll
            for (int j = 0; j < 4; j++) {
                wmma::load_matrix_sync(bf[j],
                    Bs + (wn * 64 + j * 16) * LD + kk, LD);
#pragma unroll
                for (int e = 0; e < bf[j].num_elements; e++)
                    bf[j].x[e] = wmma::__float_to_tf32(bf[j].x[e]);
            }
#pragma unroll
            for (int i = 0; i < 2; i++)
#pragma unroll
                for (int j = 0; j < 4; j++)
                    wmma::mma_sync(cf[i][j], af[i], bf[j], cf[i][j]);
        }
    }

    // epilogue: dump C to smem (A/B buffers are dead), then row max/min
    __syncthreads();
#pragma unroll
    for (int i = 0; i < 2; i++)
#pragma unroll
        for (int j = 0; j < 4; j++)
            wmma::store_matrix_sync(
                Cs + (wm * 32 + i * 16) * BN + wn * 64 + j * 16,
                cf[i][j], BN, wmma::mem_row_major);
    __syncthreads();

    const int r = t >> 1;            // 0..127
    const int h = t & 1;             // half of the row
    const float sm = g_sq[m0 + r];
    const int   lm = g_lbl[m0 + r];
    float mp = 0.f;
    float mn = __int_as_float(0x7F800000);
    const float* crow = Cs + r * BN + h * 64;
    const float* sq2  = sqn + h * 64;
    const int*   lb2  = lbn + h * 64;
#pragma unroll
    for (int c = 0; c < 64; c++) {
        float d2   = sm + sq2[c] - 2.f * crow[c];
        float dist = sqrtf(fmaxf(d2, 0.f));
        if (lm == lb2[c]) mp = fmaxf(mp, dist);
        else              mn = fminf(mn, dist);
    }
    mp = fmaxf(mp, __shfl_xor_sync(0xffffffffu, mp, 1));
    mn = fminf(mn, __shfl_xor_sync(0xffffffffu, mn, 1));
    if (h == 0) {
        atomicMax(&g_ap[m0 + r], __float_as_uint(mp));
        atomicMin(&g_an[m0 + r], __float_as_uint(mn));
    }
}

// ---- kernel 2: mean hinge ----
__global__ void k_final(float* __restrict__ out, int n) {
    float s = 0.f;
    for (int i = threadIdx.x; i < n; i += blockDim.x) {
        float ap = __uint_as_float(g_ap[i]);
        float an = __uint_as_float(g_an[i]);
        s += fmaxf(ap - an + 0.3f, 0.f);
    }
    __shared__ float sh[32];
    for (int o = 16; o > 0; o >>= 1) s += __shfl_xor_sync(0xffffffffu, s, o);
    if ((threadIdx.x & 31) == 0) sh[threadIdx.x >> 5] = s;
    __syncthreads();
    if (threadIdx.x < 32) {
        float v = (threadIdx.x < (blockDim.x >> 5)) ? sh[threadIdx.x] : 0.f;
        for (int o = 16; o > 0; o >>= 1) v += __shfl_xor_sync(0xffffffffu, v, o);
        if (threadIdx.x == 0) out[0] = v / (float)n;
    }
}

extern "C" void kernel_launch(void* const* d_in, const int* in_sizes, int n_in,
                              void* d_out, int out_size) {
    const float* X = (const float*)d_in[0];
    const void*  Y = d_in[1];
    int n = in_sizes[1];                 // 4096
    int d = in_sizes[0] / n;             // 2048
    float* out = (float*)d_out;

    static int smem_set = 0;
    if (!smem_set) {
        cudaFuncSetAttribute(k_wmma,
                             cudaFuncAttributeMaxDynamicSharedMemorySize,
                             SMEM_BYTES);
        smem_set = 1;
    }

    k_detect<<<1, 32>>>((const int*)Y);
    k_rowsq<<<n, 256>>>(X, Y, n, d);

    dim3 grid(n / BN, n / BM);
    k_wmma<<<grid, 256, SMEM_BYTES>>>(X, n, d);

    k_final<<<1, 256>>>(out, n);
}

// round 5
// speedup vs baseline: 6.2230x; 4.8076x over previous
#include <cuda_runtime.h>
#include <cuda_bf16.h>
#include <mma.h>
#include <cstdint>

using namespace nvcuda;

// ---------------------------------------------------------------------------
// TripletHardLoss: loss = mean(relu(max_{same}(dist) - min_{diff}(dist) + 0.3))
// dist[i][j] = sqrt(max(||xi||^2 + ||xj||^2 - 2 xi.xj, 0))
// Gram via bf16 WMMA, symmetric: only lower-triangle tiles computed; each
// off-diag tile feeds both row-anchor and column-anchor reductions.
// ---------------------------------------------------------------------------

#define MAX_N 4096
#define MAX_D 2048

__device__ float           g_sq[MAX_N];
__device__ unsigned int    g_ap[MAX_N];
__device__ unsigned int    g_an[MAX_N];
__device__ int             g_lbl[MAX_N];
__device__ int             g_is64;
__device__ __nv_bfloat16   g_xb[(size_t)MAX_N * MAX_D];

// ---- tiling ----
#define BM 128
#define BN 128
#define KT 64                 // K per smem stage
#define LDA 72                // bf16 stage row stride (pad 8)
#define LDC 132               // fp32 C row stride (pad 4, %4==0 for wmma store)
// smem: C tile (128*132 fp32 = 67584B) aliases A/B stages (2*128*72*2 = 36864B)
#define OFF_META 67584        // bytes: sqm[128], sqn[128], lbm[128], lbn[128]
#define SMEM_BYTES (OFF_META + 4 * 128 * 4)

// ---- kernel -1: detect label dtype ----
__global__ void k_detect(const int* __restrict__ Yi) {
    if (threadIdx.x == 0) {
        int nz = 0;
#pragma unroll
        for (int i = 0; i < 64; i++) nz |= Yi[2 * i + 1];
        g_is64 = (nz == 0) ? 1 : 0;
    }
}

// ---- kernel 0: row sum-of-squares + init + label narrow ----
__global__ void k_rowsq(const float* __restrict__ X,
                        const void* __restrict__ Y,
                        int n, int d) {
    int row = blockIdx.x;
    const float4* xr = reinterpret_cast<const float4*>(X + (size_t)row * d);
    int nv = d >> 2;
    float s = 0.f;
    for (int i = threadIdx.x; i < nv; i += blockDim.x) {
        float4 v = xr[i];
        s += v.x * v.x + v.y * v.y + v.z * v.z + v.w * v.w;
    }
    __shared__ float sh[32];
    for (int o = 16; o > 0; o >>= 1) s += __shfl_xor_sync(0xffffffffu, s, o);
    if ((threadIdx.x & 31) == 0) sh[threadIdx.x >> 5] = s;
    __syncthreads();
    if (threadIdx.x < 32) {
        float v = (threadIdx.x < (blockDim.x >> 5)) ? sh[threadIdx.x] : 0.f;
        for (int o = 16; o > 0; o >>= 1) v += __shfl_xor_sync(0xffffffffu, v, o);
        if (threadIdx.x == 0) {
            g_sq[row]  = v;
            g_ap[row]  = 0u;
            g_an[row]  = 0x7F800000u;
            g_lbl[row] = g_is64
                ? (int)reinterpret_cast<const long long*>(Y)[row]
                : reinterpret_cast<const int*>(Y)[row];
        }
    }
}

// ---- kernel 1: X (fp32) -> g_xb (bf16) ----
__global__ void k_tobf16(const float* __restrict__ X, int total4) {
    int stride = gridDim.x * blockDim.x;
    __nv_bfloat162* dst = reinterpret_cast<__nv_bfloat162*>(g_xb);
    for (int idx = blockIdx.x * blockDim.x + threadIdx.x; idx < total4;
         idx += stride) {
        float4 v = reinterpret_cast<const float4*>(X)[idx];
        dst[idx * 2 + 0] = __nv_bfloat162(__float2bfloat16(v.x),
                                          __float2bfloat16(v.y));
        dst[idx * 2 + 1] = __nv_bfloat162(__float2bfloat16(v.z),
                                          __float2bfloat16(v.w));
    }
}

// ---- kernel 2: fused bf16-WMMA triangular Gram + masked max/min ----
__global__ __launch_bounds__(256)
void k_wmma(int n, int d) {
    extern __shared__ __align__(16) char smem[];
    __nv_bfloat16* As = reinterpret_cast<__nv_bfloat16*>(smem);
    __nv_bfloat16* Bs = As + BM * LDA;
    float* Cs  = reinterpret_cast<float*>(smem);
    float* sqm = reinterpret_cast<float*>(smem + OFF_META);
    float* sqn = sqm + 128;
    int*   lbm = reinterpret_cast<int*>(sqn + 128);
    int*   lbn = lbm + 128;

    // triangular tile decode: block b -> (i >= j)
    int b = blockIdx.x;
    int i = (int)((sqrtf(8.0f * (float)b + 1.0f) - 1.0f) * 0.5f);
    while ((i + 1) * (i + 2) / 2 <= b) i++;
    while (i * (i + 1) / 2 > b) i--;
    int j = b - i * (i + 1) / 2;
    const int m0 = i * BM;
    const int n0 = j * BN;

    const int t   = threadIdx.x;
    const int wid = t >> 5;
    const int wm  = wid & 3;     // 32-row slab
    const int wn  = wid >> 2;    // 64-col slab

    if (t < 128) {
        sqm[t] = g_sq[m0 + t];
        lbm[t] = g_lbl[m0 + t];
    } else {
        int c = t - 128;
        sqn[c] = g_sq[n0 + c];
        lbn[c] = g_lbl[n0 + c];
    }

    wmma::fragment<wmma::accumulator, 16, 16, 16, float> cf[2][4];
#pragma unroll
    for (int a = 0; a < 2; a++)
#pragma unroll
        for (int c = 0; c < 4; c++) wmma::fill_fragment(cf[a][c], 0.0f);

    const __nv_bfloat16* Am = g_xb + (size_t)m0 * d;
    const __nv_bfloat16* Bn = g_xb + (size_t)n0 * d;

    for (int k0 = 0; k0 < d; k0 += KT) {
        __syncthreads();
        // stage: 128 rows x 64 bf16 per matrix, 16B chunks, 4 per thread each
#pragma unroll
        for (int q = 0; q < 4; q++) {
            int chunk = t + q * 256;          // 0..1023
            int row   = chunk >> 3;
            int c8    = (chunk & 7) * 8;      // bf16 col
            *reinterpret_cast<uint4*>(As + row * LDA + c8) =
                *reinterpret_cast<const uint4*>(Am + (size_t)row * d + k0 + c8);
            *reinterpret_cast<uint4*>(Bs + row * LDA + c8) =
                *reinterpret_cast<const uint4*>(Bn + (size_t)row * d + k0 + c8);
        }
        __syncthreads();

#pragma unroll
        for (int kk = 0; kk < KT; kk += 16) {
            wmma::fragment<wmma::matrix_a, 16, 16, 16, __nv_bfloat16,
                           wmma::row_major> af[2];
            wmma::fragment<wmma::matrix_b, 16, 16, 16, __nv_bfloat16,
                           wmma::col_major> bf[4];
#pragma unroll
            for (int a = 0; a < 2; a++)
                wmma::load_matrix_sync(af[a],
                    As + (wm * 32 + a * 16) * LDA + kk, LDA);
#pragma unroll
            for (int c = 0; c < 4; c++)
                wmma::load_matrix_sync(bf[c],
                    Bs + (wn * 64 + c * 16) * LDA + kk, LDA);
#pragma unroll
            for (int a = 0; a < 2; a++)
#pragma unroll
                for (int c = 0; c < 4; c++)
                    wmma::mma_sync(cf[a][c], af[a], bf[c], cf[a][c]);
        }
    }

    __syncthreads();   // stage buffers dead; reuse as C
#pragma unroll
    for (int a = 0; a < 2; a++)
#pragma unroll
        for (int c = 0; c < 4; c++)
            wmma::store_matrix_sync(
                Cs + (wm * 32 + a * 16) * LDC + wn * 64 + c * 16,
                cf[a][c], LDC, wmma::mem_row_major);
    __syncthreads();

    const float INF = __int_as_float(0x7F800000);

    // row anchors: thread pair per row, 64 cols each
    {
        const int r = t >> 1, h = t & 1;
        const float sm = sqm[r];
        const int   lm = lbm[r];
        float mp = 0.f, mn = INF;
        const float* crow = Cs + r * LDC + h * 64;
        const float* sq2  = sqn + h * 64;
        const int*   lb2  = lbn + h * 64;
#pragma unroll
        for (int c = 0; c < 64; c++) {
            float d2   = sm + sq2[c] - 2.f * crow[c];
            float dist = sqrtf(fmaxf(d2, 0.f));
            if (lm == lb2[c]) mp = fmaxf(mp, dist);
            else              mn = fminf(mn, dist);
        }
        mp = fmaxf(mp, __shfl_xor_sync(0xffffffffu, mp, 1));
        mn = fminf(mn, __shfl_xor_sync(0xffffffffu, mn, 1));
        if (h == 0) {
            atomicMax(&g_ap[m0 + r], __float_as_uint(mp));
            atomicMin(&g_an[m0 + r], __float_as_uint(mn));
        }
    }

    // column anchors (off-diagonal coverage of the symmetric half)
    if (m0 != n0) {
        const int c = t >> 1, h = t & 1;
        const float sc = sqn[c];
        const int   lc = lbn[c];
        float mp = 0.f, mn = INF;
        const float* ccol = Cs + (h * 64) * LDC + c;
        const float* sq2  = sqm + h * 64;
        const int*   lb2  = lbm + h * 64;
#pragma unroll
        for (int r = 0; r < 64; r++) {
            float d2   = sc + sq2[r] - 2.f * ccol[r * LDC];
            float dist = sqrtf(fmaxf(d2, 0.f));
            if (lc == lb2[r]) mp = fmaxf(mp, dist);
            else              mn = fminf(mn, dist);
        }
        mp = fmaxf(mp, __shfl_xor_sync(0xffffffffu, mp, 1));
        mn = fminf(mn, __shfl_xor_sync(0xffffffffu, mn, 1));
        if (h == 0) {
            atomicMax(&g_ap[n0 + c], __float_as_uint(mp));
            atomicMin(&g_an[n0 + c], __float_as_uint(mn));
        }
    }
}

// ---- kernel 3: mean hinge ----
__global__ void k_final(float* __restrict__ out, int n) {
    float s = 0.f;
    for (int i = threadIdx.x; i < n; i += blockDim.x) {
        float ap = __uint_as_float(g_ap[i]);
        float an = __uint_as_float(g_an[i]);
        s += fmaxf(ap - an + 0.3f, 0.f);
    }
    __shared__ float sh[32];
    for (int o = 16; o > 0; o >>= 1) s += __shfl_xor_sync(0xffffffffu, s, o);
    if ((threadIdx.x & 31) == 0) sh[threadIdx.x >> 5] = s;
    __syncthreads();
    if (threadIdx.x < 32) {
        float v = (threadIdx.x < (blockDim.x >> 5)) ? sh[threadIdx.x] : 0.f;
        for (int o = 16; o > 0; o >>= 1) v += __shfl_xor_sync(0xffffffffu, v, o);
        if (threadIdx.x == 0) out[0] = v / (float)n;
    }
}

extern "C" void kernel_launch(void* const* d_in, const int* in_sizes, int n_in,
                              void* d_out, int out_size) {
    const float* X = (const float*)d_in[0];
    const void*  Y = d_in[1];
    int n = in_sizes[1];                 // 4096
    int d = in_sizes[0] / n;             // 2048
    float* out = (float*)d_out;

    static int smem_set = 0;
    if (!smem_set) {
        cudaFuncSetAttribute(k_wmma,
                             cudaFuncAttributeMaxDynamicSharedMemorySize,
                             SMEM_BYTES);
        smem_set = 1;
    }

    k_detect<<<1, 32>>>((const int*)Y);
    k_rowsq<<<n, 256>>>(X, Y, n, d);
    k_tobf16<<<1024, 256>>>(X, (n * d) / 4);

    int nt = n / BM;
    int nblocks = nt * (nt + 1) / 2;     // 528
    k_wmma<<<nblocks, 256, SMEM_BYTES>>>(n, d);

    k_final<<<1, 256>>>(out, n);
}

// round 7
// speedup vs baseline: 6.6565x; 1.0697x over previous
#include <cuda_runtime.h>
#include <cuda_bf16.h>
#include <mma.h>
#include <cstdint>

using namespace nvcuda;

// ---------------------------------------------------------------------------
// TripletHardLoss: loss = mean(relu(max_{same}(dist) - min_{diff}(dist) + 0.3))
// dist[i][j] = sqrt(max(||xi||^2 + ||xj||^2 - 2 xi.xj, 0))
// bf16 WMMA Gram, triangular tiles (symmetry), cp.async double-buffered
// pipeline, 2 CTAs/SM via launch_bounds.
// R6 fix: cp.async stage mapping now covers all 64 K-columns (4 chunks/thread).
// ---------------------------------------------------------------------------

#define MAX_N 4096
#define MAX_D 2048

__device__ float           g_sq[MAX_N];
__device__ unsigned int    g_ap[MAX_N];
__device__ unsigned int    g_an[MAX_N];
__device__ int             g_lbl[MAX_N];
__device__ int             g_is64;
__device__ __nv_bfloat16   g_xb[(size_t)MAX_N * MAX_D];

// ---- tiling ----
#define BM 128
#define BN 128
#define KT 64                 // K per smem stage
#define LDA 72                // bf16 stage row stride (pad 8), 144B %16==0
#define LDC 132               // fp32 C row stride
#define STAGE_HALF (BM * LDA)             // bf16 elems per matrix per stage
#define STAGE_ELEMS (2 * STAGE_HALF)      // A+B per stage
// smem: stages [2][A+B] = 73728B; C tile (67584B) aliases them; meta after
#define OFF_META 73728
#define SMEM_BYTES (OFF_META + 4 * 128 * 4)

__device__ __forceinline__ uint32_t smem_u32(const void* p) {
    uint32_t a;
    asm("{ .reg .u64 t; cvta.to.shared.u64 t, %1; cvt.u32.u64 %0, t; }"
        : "=r"(a) : "l"(p));
    return a;
}
__device__ __forceinline__ void cp_async16(uint32_t dst, const void* src) {
    asm volatile("cp.async.cg.shared.global [%0], [%1], 16;"
                 :: "r"(dst), "l"(src) : "memory");
}

// ---- kernel -1: detect label dtype ----
__global__ void k_detect(const int* __restrict__ Yi) {
    if (threadIdx.x == 0) {
        int nz = 0;
#pragma unroll
        for (int i = 0; i < 64; i++) nz |= Yi[2 * i + 1];
        g_is64 = (nz == 0) ? 1 : 0;
    }
}

// ---- kernel 0: row sum-of-squares + init + label narrow ----
__global__ void k_rowsq(const float* __restrict__ X,
                        const void* __restrict__ Y,
                        int n, int d) {
    int row = blockIdx.x;
    const float4* xr = reinterpret_cast<const float4*>(X + (size_t)row * d);
    int nv = d >> 2;
    float s = 0.f;
    for (int i = threadIdx.x; i < nv; i += blockDim.x) {
        float4 v = xr[i];
        s += v.x * v.x + v.y * v.y + v.z * v.z + v.w * v.w;
    }
    __shared__ float sh[32];
    for (int o = 16; o > 0; o >>= 1) s += __shfl_xor_sync(0xffffffffu, s, o);
    if ((threadIdx.x & 31) == 0) sh[threadIdx.x >> 5] = s;
    __syncthreads();
    if (threadIdx.x < 32) {
        float v = (threadIdx.x < (blockDim.x >> 5)) ? sh[threadIdx.x] : 0.f;
        for (int o = 16; o > 0; o >>= 1) v += __shfl_xor_sync(0xffffffffu, v, o);
        if (threadIdx.x == 0) {
            g_sq[row]  = v;
            g_ap[row]  = 0u;
            g_an[row]  = 0x7F800000u;
            g_lbl[row] = g_is64
                ? (int)reinterpret_cast<const long long*>(Y)[row]
                : reinterpret_cast<const int*>(Y)[row];
        }
    }
}

// ---- kernel 1: X (fp32) -> g_xb (bf16) ----
__global__ void k_tobf16(const float* __restrict__ X, int total4) {
    int stride = gridDim.x * blockDim.x;
    __nv_bfloat162* dst = reinterpret_cast<__nv_bfloat162*>(g_xb);
    for (int idx = blockIdx.x * blockDim.x + threadIdx.x; idx < total4;
         idx += stride) {
        float4 v = reinterpret_cast<const float4*>(X)[idx];
        dst[idx * 2 + 0] = __nv_bfloat162(__float2bfloat16(v.x),
                                          __float2bfloat16(v.y));
        dst[idx * 2 + 1] = __nv_bfloat162(__float2bfloat16(v.z),
                                          __float2bfloat16(v.w));
    }
}

// ---- kernel 2: pipelined bf16-WMMA triangular Gram + masked max/min ----
__global__ __launch_bounds__(256, 2)
void k_wmma(int n, int d) {
    extern __shared__ __align__(16) char smem[];
    __nv_bfloat16* stage = reinterpret_cast<__nv_bfloat16*>(smem);
    float* Cs  = reinterpret_cast<float*>(smem);
    float* sqm = reinterpret_cast<float*>(smem + OFF_META);
    float* sqn = sqm + 128;
    int*   lbm = reinterpret_cast<int*>(sqn + 128);
    int*   lbn = lbm + 128;

    // triangular tile decode: block b -> (i >= j)
    int b = blockIdx.x;
    int i = (int)((sqrtf(8.0f * (float)b + 1.0f) - 1.0f) * 0.5f);
    while ((i + 1) * (i + 2) / 2 <= b) i++;
    while (i * (i + 1) / 2 > b) i--;
    int j = b - i * (i + 1) / 2;
    const int m0 = i * BM;
    const int n0 = j * BN;

    const int t   = threadIdx.x;
    const int wid = t >> 5;
    const int wm  = wid & 3;     // 32-row slab
    const int wn  = wid >> 2;    // 64-col slab

    if (t < 128) {
        sqm[t] = g_sq[m0 + t];
        lbm[t] = g_lbl[m0 + t];
    } else {
        int c = t - 128;
        sqn[c] = g_sq[n0 + c];
        lbn[c] = g_lbl[n0 + c];
    }

    const __nv_bfloat16* Am = g_xb + (size_t)m0 * d;
    const __nv_bfloat16* Bn = g_xb + (size_t)n0 * d;

    // per-thread load mapping: 4 chunks/matrix, chunk = 16B = 8 bf16
    // row = t>>1 (0..127); cols (t&1)*32 + q*8, q=0..3  -> full 0..63 coverage
    const int lrow = t >> 1;
    const int lc0  = (t & 1) * 32;

    auto issue_stage = [&](int it, int buf) {
        const int k0 = it * KT;
        __nv_bfloat16* SA = stage + buf * STAGE_ELEMS;
        __nv_bfloat16* SB = SA + STAGE_HALF;
        uint32_t sa = smem_u32(SA);
        uint32_t sb = smem_u32(SB);
#pragma unroll
        for (int q = 0; q < 4; q++) {
            int c8 = lc0 + q * 8;            // bf16 col within stage
            uint32_t so = (uint32_t)(lrow * LDA + c8) * 2;
            cp_async16(sa + so, Am + (size_t)lrow * d + k0 + c8);
            cp_async16(sb + so, Bn + (size_t)lrow * d + k0 + c8);
        }
        asm volatile("cp.async.commit_group;" ::: "memory");
    };

    wmma::fragment<wmma::accumulator, 16, 16, 16, float> cf[2][4];
#pragma unroll
    for (int a = 0; a < 2; a++)
#pragma unroll
        for (int c = 0; c < 4; c++) wmma::fill_fragment(cf[a][c], 0.0f);

    const int nIter = d / KT;
    issue_stage(0, 0);

    for (int it = 0; it < nIter; it++) {
        const int buf = it & 1;
        if (it + 1 < nIter) {
            issue_stage(it + 1, buf ^ 1);
            asm volatile("cp.async.wait_group 1;" ::: "memory");
        } else {
            asm volatile("cp.async.wait_group 0;" ::: "memory");
        }
        __syncthreads();

        const __nv_bfloat16* As = stage + buf * STAGE_ELEMS;
        const __nv_bfloat16* Bs = As + STAGE_HALF;
#pragma unroll
        for (int kk = 0; kk < KT; kk += 16) {
            wmma::fragment<wmma::matrix_a, 16, 16, 16, __nv_bfloat16,
                           wmma::row_major> af[2];
            wmma::fragment<wmma::matrix_b, 16, 16, 16, __nv_bfloat16,
                           wmma::col_major> bf[4];
#pragma unroll
            for (int a = 0; a < 2; a++)
                wmma::load_matrix_sync(af[a],
                    As + (wm * 32 + a * 16) * LDA + kk, LDA);
#pragma unroll
            for (int c = 0; c < 4; c++)
                wmma::load_matrix_sync(bf[c],
                    Bs + (wn * 64 + c * 16) * LDA + kk, LDA);
#pragma unroll
            for (int a = 0; a < 2; a++)
#pragma unroll
                for (int c = 0; c < 4; c++)
                    wmma::mma_sync(cf[a][c], af[a], bf[c], cf[a][c]);
        }
        __syncthreads();   // compute on buf done before it is refilled
    }

    // epilogue: stage buffers dead; reuse as C
#pragma unroll
    for (int a = 0; a < 2; a++)
#pragma unroll
        for (int c = 0; c < 4; c++)
            wmma::store_matrix_sync(
                Cs + (wm * 32 + a * 16) * LDC + wn * 64 + c * 16,
                cf[a][c], LDC, wmma::mem_row_major);
    __syncthreads();

    const float INF = __int_as_float(0x7F800000);

    // row anchors: thread pair per row, 64 cols each
    {
        const int r = t >> 1, h = t & 1;
        const float sm = sqm[r];
        const int   lm = lbm[r];
        float mp = 0.f, mn = INF;
        const float* crow = Cs + r * LDC + h * 64;
        const float* sq2  = sqn + h * 64;
        const int*   lb2  = lbn + h * 64;
#pragma unroll
        for (int c = 0; c < 64; c++) {
            float d2   = sm + sq2[c] - 2.f * crow[c];
            float dist = sqrtf(fmaxf(d2, 0.f));
            if (lm == lb2[c]) mp = fmaxf(mp, dist);
            else              mn = fminf(mn, dist);
        }
        mp = fmaxf(mp, __shfl_xor_sync(0xffffffffu, mp, 1));
        mn = fminf(mn, __shfl_xor_sync(0xffffffffu, mn, 1));
        if (h == 0) {
            atomicMax(&g_ap[m0 + r], __float_as_uint(mp));
            atomicMin(&g_an[m0 + r], __float_as_uint(mn));
        }
    }

    // column anchors (off-diagonal coverage of the symmetric half)
    if (m0 != n0) {
        const int c = t >> 1, h = t & 1;
        const float sc = sqn[c];
        const int   lc = lbn[c];
        float mp = 0.f, mn = INF;
        const float* ccol = Cs + (h * 64) * LDC + c;
        const float* sq2  = sqm + h * 64;
        const int*   lb2  = lbm + h * 64;
#pragma unroll
        for (int r = 0; r < 64; r++) {
            float d2   = sc + sq2[r] - 2.f * ccol[r * LDC];
            float dist = sqrtf(fmaxf(d2, 0.f));
            if (lc == lb2[r]) mp = fmaxf(mp, dist);
            else              mn = fminf(mn, dist);
        }
        mp = fmaxf(mp, __shfl_xor_sync(0xffffffffu, mp, 1));
        mn = fminf(mn, __shfl_xor_sync(0xffffffffu, mn, 1));
        if (h == 0) {
            atomicMax(&g_ap[n0 + c], __float_as_uint(mp));
            atomicMin(&g_an[n0 + c], __float_as_uint(mn));
        }
    }
}

// ---- kernel 3: mean hinge ----
__global__ void k_final(float* __restrict__ out, int n) {
    float s = 0.f;
    for (int i = threadIdx.x; i < n; i += blockDim.x) {
        float ap = __uint_as_float(g_ap[i]);
        float an = __uint_as_float(g_an[i]);
        s += fmaxf(ap - an + 0.3f, 0.f);
    }
    __shared__ float sh[32];
    for (int o = 16; o > 0; o >>= 1) s += __shfl_xor_sync(0xffffffffu, s, o);
    if ((threadIdx.x & 31) == 0) sh[threadIdx.x >> 5] = s;
    __syncthreads();
    if (threadIdx.x < 32) {
        float v = (threadIdx.x < (blockDim.x >> 5)) ? sh[threadIdx.x] : 0.f;
        for (int o = 16; o > 0; o >>= 1) v += __shfl_xor_sync(0xffffffffu, v, o);
        if (threadIdx.x == 0) out[0] = v / (float)n;
    }
}

extern "C" void kernel_launch(void* const* d_in, const int* in_sizes, int n_in,
                              void* d_out, int out_size) {
    const float* X = (const float*)d_in[0];
    const void*  Y = d_in[1];
    int n = in_sizes[1];                 // 4096
    int d = in_sizes[0] / n;             // 2048
    float* out = (float*)d_out;

    static int smem_set = 0;
    if (!smem_set) {
        cudaFuncSetAttribute(k_wmma,
                             cudaFuncAttributeMaxDynamicSharedMemorySize,
                             SMEM_BYTES);
        smem_set = 1;
    }

    k_detect<<<1, 32>>>((const int*)Y);
    k_rowsq<<<n, 256>>>(X, Y, n, d);
    k_tobf16<<<1024, 256>>>(X, (n * d) / 4);

    int nt = n / BM;
    int nblocks = nt * (nt + 1) / 2;     // 528
    k_wmma<<<nblocks, 256, SMEM_BYTES>>>(n, d);

    k_final<<<1, 256>>>(out, n);
}

// round 8
// speedup vs baseline: 6.7178x; 1.0092x over previous
#include <cuda_runtime.h>
#include <cuda_bf16.h>
#include <mma.h>
#include <cstdint>

using namespace nvcuda;

// ---------------------------------------------------------------------------
// TripletHardLoss: loss = mean(relu(max_{same}(dist) - min_{diff}(dist) + 0.3))
// dist[i][j] = sqrt(max(||xi||^2 + ||xj||^2 - 2 xi.xj, 0))
// bf16 WMMA Gram, triangular tiles (symmetry), 3-stage cp.async pipeline with
// a single __syncthreads per K-stage, 2 CTAs/SM.
// ---------------------------------------------------------------------------

#define MAX_N 4096
#define MAX_D 2048

__device__ float           g_sq[MAX_N];
__device__ unsigned int    g_ap[MAX_N];
__device__ unsigned int    g_an[MAX_N];
__device__ int             g_lbl[MAX_N];
__device__ int             g_is64;
__device__ __nv_bfloat16   g_xb[(size_t)MAX_N * MAX_D];

// ---- tiling ----
#define BM 128
#define BN 128
#define KT 64                 // K per smem stage
#define LDA 72                // bf16 stage row stride (pad 8), 144B %16==0
#define LDC 132               // fp32 C row stride
#define NSTAGE 3
#define STAGE_HALF (BM * LDA)             // bf16 elems per matrix per stage
#define STAGE_ELEMS (2 * STAGE_HALF)      // A+B per stage (36864 B)
// smem: stages [3][A+B] = 110592B; C tile (67584B) aliases them; meta after
#define OFF_META (NSTAGE * STAGE_ELEMS * 2)
#define SMEM_BYTES (OFF_META + 4 * 128 * 4)

__device__ __forceinline__ uint32_t smem_u32(const void* p) {
    uint32_t a;
    asm("{ .reg .u64 t; cvta.to.shared.u64 t, %1; cvt.u32.u64 %0, t; }"
        : "=r"(a) : "l"(p));
    return a;
}
__device__ __forceinline__ void cp_async16(uint32_t dst, const void* src) {
    asm volatile("cp.async.cg.shared.global [%0], [%1], 16;"
                 :: "r"(dst), "l"(src) : "memory");
}

// ---- kernel -1: detect label dtype ----
__global__ void k_detect(const int* __restrict__ Yi) {
    if (threadIdx.x == 0) {
        int nz = 0;
#pragma unroll
        for (int i = 0; i < 64; i++) nz |= Yi[2 * i + 1];
        g_is64 = (nz == 0) ? 1 : 0;
    }
}

// ---- kernel 0: row sum-of-squares + init + label narrow ----
__global__ void k_rowsq(const float* __restrict__ X,
                        const void* __restrict__ Y,
                        int n, int d) {
    int row = blockIdx.x;
    const float4* xr = reinterpret_cast<const float4*>(X + (size_t)row * d);
    int nv = d >> 2;
    float s = 0.f;
    for (int i = threadIdx.x; i < nv; i += blockDim.x) {
        float4 v = xr[i];
        s += v.x * v.x + v.y * v.y + v.z * v.z + v.w * v.w;
    }
    __shared__ float sh[32];
    for (int o = 16; o > 0; o >>= 1) s += __shfl_xor_sync(0xffffffffu, s, o);
    if ((threadIdx.x & 31) == 0) sh[threadIdx.x >> 5] = s;
    __syncthreads();
    if (threadIdx.x < 32) {
        float v = (threadIdx.x < (blockDim.x >> 5)) ? sh[threadIdx.x] : 0.f;
        for (int o = 16; o > 0; o >>= 1) v += __shfl_xor_sync(0xffffffffu, v, o);
        if (threadIdx.x == 0) {
            g_sq[row]  = v;
            g_ap[row]  = 0u;
            g_an[row]  = 0x7F800000u;
            g_lbl[row] = g_is64
                ? (int)reinterpret_cast<const long long*>(Y)[row]
                : reinterpret_cast<const int*>(Y)[row];
        }
    }
}

// ---- kernel 1: X (fp32) -> g_xb (bf16) ----
__global__ void k_tobf16(const float* __restrict__ X, int total4) {
    int stride = gridDim.x * blockDim.x;
    __nv_bfloat162* dst = reinterpret_cast<__nv_bfloat162*>(g_xb);
    for (int idx = blockIdx.x * blockDim.x + threadIdx.x; idx < total4;
         idx += stride) {
        float4 v = reinterpret_cast<const float4*>(X)[idx];
        dst[idx * 2 + 0] = __nv_bfloat162(__float2bfloat16(v.x),
                                          __float2bfloat16(v.y));
        dst[idx * 2 + 1] = __nv_bfloat162(__float2bfloat16(v.z),
                                          __float2bfloat16(v.w));
    }
}

// ---- kernel 2: 3-stage pipelined bf16-WMMA triangular Gram + max/min ----
__global__ __launch_bounds__(256, 2)
void k_wmma(int n, int d) {
    extern __shared__ __align__(16) char smem[];
    __nv_bfloat16* stage = reinterpret_cast<__nv_bfloat16*>(smem);
    float* Cs  = reinterpret_cast<float*>(smem);
    float* sqm = reinterpret_cast<float*>(smem + OFF_META);
    float* sqn = sqm + 128;
    int*   lbm = reinterpret_cast<int*>(sqn + 128);
    int*   lbn = lbm + 128;

    // triangular tile decode: block b -> (i >= j)
    int b = blockIdx.x;
    int i = (int)((sqrtf(8.0f * (float)b + 1.0f) - 1.0f) * 0.5f);
    while ((i + 1) * (i + 2) / 2 <= b) i++;
    while (i * (i + 1) / 2 > b) i--;
    int j = b - i * (i + 1) / 2;
    const int m0 = i * BM;
    const int n0 = j * BN;

    const int t   = threadIdx.x;
    const int wid = t >> 5;
    const int wm  = wid & 3;     // 32-row slab
    const int wn  = wid >> 2;    // 64-col slab

    if (t < 128) {
        sqm[t] = g_sq[m0 + t];
        lbm[t] = g_lbl[m0 + t];
    } else {
        int c = t - 128;
        sqn[c] = g_sq[n0 + c];
        lbn[c] = g_lbl[n0 + c];
    }

    const __nv_bfloat16* Am = g_xb + (size_t)m0 * d;
    const __nv_bfloat16* Bn = g_xb + (size_t)n0 * d;

    // per-thread load mapping: row = t>>1; cols (t&1)*32 + q*8, q=0..3
    const int lrow = t >> 1;
    const int lc0  = (t & 1) * 32;

    auto issue_stage = [&](int it, int buf) {
        const int k0 = it * KT;
        __nv_bfloat16* SA = stage + buf * STAGE_ELEMS;
        __nv_bfloat16* SB = SA + STAGE_HALF;
        uint32_t sa = smem_u32(SA);
        uint32_t sb = smem_u32(SB);
#pragma unroll
        for (int q = 0; q < 4; q++) {
            int c8 = lc0 + q * 8;
            uint32_t so = (uint32_t)(lrow * LDA + c8) * 2;
            cp_async16(sa + so, Am + (size_t)lrow * d + k0 + c8);
            cp_async16(sb + so, Bn + (size_t)lrow * d + k0 + c8);
        }
        asm volatile("cp.async.commit_group;" ::: "memory");
    };

    wmma::fragment<wmma::accumulator, 16, 16, 16, float> cf[2][4];
#pragma unroll
    for (int a = 0; a < 2; a++)
#pragma unroll
        for (int c = 0; c < 4; c++) wmma::fill_fragment(cf[a][c], 0.0f);

    const int nIter = d / KT;
    issue_stage(0, 0);
    issue_stage(1, 1);

    int buf = 0;
    for (int it = 0; it < nIter; it++) {
        // retire to: stage `it` complete. In flight: it .. min(it+1, nIter-1)
        if (it + 1 < nIter)
            asm volatile("cp.async.wait_group 1;" ::: "memory");
        else
            asm volatile("cp.async.wait_group 0;" ::: "memory");
        // single barrier: data for `it` visible to all warps AND every warp
        // finished compute(it-1), so buffer (it+2)%3 == (it-1)%3 is free.
        __syncthreads();
        if (it + 2 < nIter) {
            int nb = buf + 2;
            if (nb >= NSTAGE) nb -= NSTAGE;
            issue_stage(it + 2, nb);
        }

        const __nv_bfloat16* As = stage + buf * STAGE_ELEMS;
        const __nv_bfloat16* Bs = As + STAGE_HALF;
#pragma unroll
        for (int kk = 0; kk < KT; kk += 16) {
            wmma::fragment<wmma::matrix_a, 16, 16, 16, __nv_bfloat16,
                           wmma::row_major> af[2];
            wmma::fragment<wmma::matrix_b, 16, 16, 16, __nv_bfloat16,
                           wmma::col_major> bf[4];
#pragma unroll
            for (int a = 0; a < 2; a++)
                wmma::load_matrix_sync(af[a],
                    As + (wm * 32 + a * 16) * LDA + kk, LDA);
#pragma unroll
            for (int c = 0; c < 4; c++)
                wmma::load_matrix_sync(bf[c],
                    Bs + (wn * 64 + c * 16) * LDA + kk, LDA);
#pragma unroll
            for (int a = 0; a < 2; a++)
#pragma unroll
                for (int c = 0; c < 4; c++)
                    wmma::mma_sync(cf[a][c], af[a], bf[c], cf[a][c]);
        }
        if (++buf == NSTAGE) buf = 0;
    }

    // epilogue: stage buffers dead; reuse as C
    __syncthreads();
#pragma unroll
    for (int a = 0; a < 2; a++)
#pragma unroll
        for (int c = 0; c < 4; c++)
            wmma::store_matrix_sync(
                Cs + (wm * 32 + a * 16) * LDC + wn * 64 + c * 16,
                cf[a][c], LDC, wmma::mem_row_major);
    __syncthreads();

    const float INF = __int_as_float(0x7F800000);

    // row anchors: thread pair per row, 64 cols each
    {
        const int r = t >> 1, h = t & 1;
        const float sm = sqm[r];
        const int   lm = lbm[r];
        float mp = 0.f, mn = INF;
        const float* crow = Cs + r * LDC + h * 64;
        const float* sq2  = sqn + h * 64;
        const int*   lb2  = lbn + h * 64;
#pragma unroll
        for (int c = 0; c < 64; c++) {
            float d2   = sm + sq2[c] - 2.f * crow[c];
            float dist = sqrtf(fmaxf(d2, 0.f));
            if (lm == lb2[c]) mp = fmaxf(mp, dist);
            else              mn = fminf(mn, dist);
        }
        mp = fmaxf(mp, __shfl_xor_sync(0xffffffffu, mp, 1));
        mn = fminf(mn, __shfl_xor_sync(0xffffffffu, mn, 1));
        if (h == 0) {
            atomicMax(&g_ap[m0 + r], __float_as_uint(mp));
            atomicMin(&g_an[m0 + r], __float_as_uint(mn));
        }
    }

    // column anchors (off-diagonal coverage of the symmetric half)
    if (m0 != n0) {
        const int c = t >> 1, h = t & 1;
        const float sc = sqn[c];
        const int   lc = lbn[c];
        float mp = 0.f, mn = INF;
        const float* ccol = Cs + (h * 64) * LDC + c;
        const float* sq2  = sqm + h * 64;
        const int*   lb2  = lbm + h * 64;
#pragma unroll
        for (int r = 0; r < 64; r++) {
            float d2   = sc + sq2[r] - 2.f * ccol[r * LDC];
            float dist = sqrtf(fmaxf(d2, 0.f));
            if (lc == lb2[r]) mp = fmaxf(mp, dist);
            else              mn = fminf(mn, dist);
        }
        mp = fmaxf(mp, __shfl_xor_sync(0xffffffffu, mp, 1));
        mn = fminf(mn, __shfl_xor_sync(0xffffffffu, mn, 1));
        if (h == 0) {
            atomicMax(&g_ap[n0 + c], __float_as_uint(mp));
            atomicMin(&g_an[n0 + c], __float_as_uint(mn));
        }
    }
}

// ---- kernel 3: mean hinge ----
__global__ void k_final(float* __restrict__ out, int n) {
    float s = 0.f;
    for (int i = threadIdx.x; i < n; i += blockDim.x) {
        float ap = __uint_as_float(g_ap[i]);
        float an = __uint_as_float(g_an[i]);
        s += fmaxf(ap - an + 0.3f, 0.f);
    }
    __shared__ float sh[32];
    for (int o = 16; o > 0; o >>= 1) s += __shfl_xor_sync(0xffffffffu, s, o);
    if ((threadIdx.x & 31) == 0) sh[threadIdx.x >> 5] = s;
    __syncthreads();
    if (threadIdx.x < 32) {
        float v = (threadIdx.x < (blockDim.x >> 5)) ? sh[threadIdx.x] : 0.f;
        for (int o = 16; o > 0; o >>= 1) v += __shfl_xor_sync(0xffffffffu, v, o);
        if (threadIdx.x == 0) out[0] = v / (float)n;
    }
}

extern "C" void kernel_launch(void* const* d_in, const int* in_sizes, int n_in,
                              void* d_out, int out_size) {
    const float* X = (const float*)d_in[0];
    const void*  Y = d_in[1];
    int n = in_sizes[1];                 // 4096
    int d = in_sizes[0] / n;             // 2048
    float* out = (float*)d_out;

    static int smem_set = 0;
    if (!smem_set) {
        cudaFuncSetAttribute(k_wmma,
                             cudaFuncAttributeMaxDynamicSharedMemorySize,
                             SMEM_BYTES);
        smem_set = 1;
    }

    k_detect<<<1, 32>>>((const int*)Y);
    k_rowsq<<<n, 256>>>(X, Y, n, d);
    k_tobf16<<<1024, 256>>>(X, (n * d) / 4);

    int nt = n / BM;
    int nblocks = nt * (nt + 1) / 2;     // 528
    k_wmma<<<nblocks, 256, SMEM_BYTES>>>(n, d);

    k_final<<<1, 256>>>(out, n);
}